// round 8
// baseline (speedup 1.0000x reference)
#include <cuda_runtime.h>

#define NN 1024
#define HH 512
#define TI 32            // output rows per CTA chunk
#define WCOLS 64         // output cols per warp
#define NWARPS 8
#define NTHREADS (NWARPS*32)
#define PF2 10           // L2 prefetch distance (output rows)
#define PF1 3            // L1 prefetch distance (output rows)

__device__ __forceinline__ int reflC(int c) {
    if (c < 0) c = -c;
    if (c > HH - 1) c = 2 * (HH - 1) - c;
    return c;
}

__device__ __forceinline__ void pfL2(const float* p) {
    asm volatile("prefetch.global.L2 [%0];" :: "l"(p));
}

__device__ __forceinline__ void pfL1(const float* p) {
    asm volatile("prefetch.global.L1 [%0];" :: "l"(p));
}

__device__ __forceinline__ void stcs2(float* p, float a, float b) {
    asm volatile("st.global.cs.v2.f32 [%0], {%1,%2};" :: "l"(p), "f"(a), "f"(b) : "memory");
}

struct V4 { float s0, s1, d0, d1; };

// Shuffle-free row lift: lane owns output cols {2j, 2j+1} (raw floats 4j..4j+3).
// Three overlapping float4 loads supply the full 12-float window; neighbor data
// comes from L1 (same cache lines as adjacent lanes' loads), not SHFL.
__device__ __forceinline__ V4 rowlift(const float* __restrict__ rp,
                                      int loff, int offA, int offC,
                                      bool lEdge, bool rEdge) {
    const float4 B = *reinterpret_cast<const float4*>(rp + loff);   // raw[4j..4j+3]
    const float4 A = *reinterpret_cast<const float4*>(rp + offA);   // raw[4j-4..4j-1]
    const float4 C = *reinterpret_cast<const float4*>(rp + offC);   // raw[4j+4..4j+7]
    float dm1 = A.w - 0.5f * (A.x + B.x);   // d[2j-1]
    float d0  = B.y - 0.5f * (A.z + B.z);   // d[2j]
    float d1  = B.w - 0.5f * (B.x + C.x);   // d[2j+1]
    float d2  = C.y - 0.5f * (B.z + C.z);   // d[2j+2]
    if (lEdge) { dm1 = d1; d0 = B.y - B.z; }          // d[-1]=d[1]; even[-1]=even[1]
    if (rEdge) { d1 = B.w - B.x; d2 = d0; }           // even[512]=even[510]; d[512]=d[510]
    V4 r;
    r.s0 = B.x + 0.25f * (dm1 + d1);
    r.s1 = B.z + 0.25f * (d0 + d2);
    r.d0 = d0; r.d1 = d1;
    return r;
}

#define LIFT(rawrow) \
    rowlift(xp + (size_t)(rawrow) * NN, loff, offA, offC, lEdge, rEdge)

__global__ __launch_bounds__(NTHREADS, 3)
void ilwt2d_warp_kernel(const float* __restrict__ x, float* __restrict__ out) {
    const int lane = threadIdx.x & 31;
    const int w = threadIdx.x >> 5;
    const int C0 = w * WCOLS;
    const int i0 = blockIdx.x * TI;
    const int img = blockIdx.y;
    const float* __restrict__ xp = x + (size_t)img * NN * NN;

    const int b = img / 3, ch = img - 3 * b;
    const size_t plane = (size_t)HH * HH;
    float* __restrict__ outb = out + (size_t)b * 12 * plane + (size_t)ch * plane;
    const int ocol = C0 + 2 * lane;

    const int loff = 2 * C0 + 4 * lane;               // raw float offset 4j
    const bool lEdge = (loff == 0);
    const bool rEdge = (loff == NN - 4);              // last 4 floats of the raw row
    const int offA = lEdge ? loff : loff - 4;
    const int offC = rEdge ? loff : loff + 4;

    // -------- prologue L2 prefetch burst: rows consumed in the first PF2 iterations --------
    {
        int rlo = 2 * i0 + 3;
        #pragma unroll
        for (int r = 0; r < 2 * PF2 + 2; ++r) {
            int rr = rlo + r; if (rr > NN - 1) rr = NN - 1;
            pfL2(xp + (size_t)rr * NN + loff);
        }
    }
    // -------- prologue L1 prefetch: rows for first PF1 iterations --------
    {
        int rlo = 2 * i0 + 3;
        #pragma unroll
        for (int r = 0; r < 2 * PF1 + 2; ++r) {
            int rr = rlo + r; if (rr > NN - 1) rr = NN - 1;
            pfL1(xp + (size_t)rr * NN + loff);
        }
    }

    // -------- prologue: build column-lift pipeline state --------
    V4 Ecur  = LIFT(2 * i0);                          // E[i0]
    V4 Em    = LIFT(2 * reflC(i0 - 1));               // E[i0-1]
    V4 Em2   = LIFT(2 * reflC(i0 - 2));               // E[i0-2]
    V4 Om1   = LIFT(2 * reflC(i0 - 1) + 1);           // O[i0-1]
    V4 Dprev;                                         // Dcol[i0-1]
    Dprev.s0 = Om1.s0 - 0.5f * (Em2.s0 + Ecur.s0);
    Dprev.s1 = Om1.s1 - 0.5f * (Em2.s1 + Ecur.s1);
    Dprev.d0 = Om1.d0 - 0.5f * (Em2.d0 + Ecur.d0);
    Dprev.d1 = Om1.d1 - 0.5f * (Em2.d1 + Ecur.d1);
    V4 Enext = LIFT(2 * reflC(i0 + 1));               // E[i0+1]
    V4 O0    = LIFT(2 * i0 + 1);                      // O[i0]
    V4 Dcur;                                          // Dcol[i0]
    Dcur.s0 = O0.s0 - 0.5f * (Em.s0 + Enext.s0);
    Dcur.s1 = O0.s1 - 0.5f * (Em.s1 + Enext.s1);
    Dcur.d0 = O0.d0 - 0.5f * (Em.d0 + Enext.d0);
    Dcur.d1 = O0.d1 - 0.5f * (Em.d1 + Enext.d1);

    // -------- main streaming loop over output rows --------
    #pragma unroll 4
    for (int t = 0; t < TI; ++t) {
        const int i = i0 + t;

        // long-range: pull DRAM -> L2 for iteration i+PF2
        {
            int ra = 2 * (i + PF2) + 3; if (ra > NN - 1) ra = NN - 1;
            int rb = ra + 1;            if (rb > NN - 1) rb = NN - 1;
            pfL2(xp + (size_t)ra * NN + loff);
            pfL2(xp + (size_t)rb * NN + loff);
        }
        // short-range: pull L2 -> L1 for iteration i+PF1
        {
            int ra = 2 * (i + PF1) + 3; if (ra > NN - 1) ra = NN - 1;
            int rb = ra + 1;            if (rb > NN - 1) rb = NN - 1;
            pfL1(xp + (size_t)ra * NN + loff);
            pfL1(xp + (size_t)rb * NN + loff);
        }

        V4 En2 = LIFT(2 * reflC(i + 2));              // E[i+2]
        V4 Oi1 = LIFT(2 * reflC(i + 1) + 1);          // O[i+1]
        V4 Dnext;                                     // Dcol[i+1]
        Dnext.s0 = Oi1.s0 - 0.5f * (Ecur.s0 + En2.s0);
        Dnext.s1 = Oi1.s1 - 0.5f * (Ecur.s1 + En2.s1);
        Dnext.d0 = Oi1.d0 - 0.5f * (Ecur.d0 + En2.d0);
        Dnext.d1 = Oi1.d1 - 0.5f * (Ecur.d1 + En2.d1);

        float2 ll = { Ecur.s0 + 0.25f * (Dprev.s0 + Dnext.s0),
                      Ecur.s1 + 0.25f * (Dprev.s1 + Dnext.s1) };
        float2 hl = { Ecur.d0 + 0.25f * (Dprev.d0 + Dnext.d0),
                      Ecur.d1 + 0.25f * (Dprev.d1 + Dnext.d1) };

        float* op = outb + (size_t)i * HH + ocol;
        stcs2(op,             ll.x, ll.y);
        stcs2(op + 3 * plane, Dcur.s0, Dcur.s1);
        stcs2(op + 6 * plane, hl.x, hl.y);
        stcs2(op + 9 * plane, Dcur.d0, Dcur.d1);

        Ecur = Enext; Enext = En2;
        Dprev = Dcur; Dcur = Dnext;
    }
}

extern "C" void kernel_launch(void* const* d_in, const int* in_sizes, int n_in,
                              void* d_out, int out_size) {
    const float* x = (const float*)d_in[0];
    float* out = (float*)d_out;
    dim3 grid(HH / TI, 24);   // 16 x 24 = 384 CTAs, 8 warps each
    ilwt2d_warp_kernel<<<grid, NTHREADS>>>(x, out);
}

// round 9
// speedup vs baseline: 1.3790x; 1.3790x over previous
#include <cuda_runtime.h>
#include <cstdint>

#define NN 1024
#define HH 512
#define TI 32            // output rows per CTA
#define NWARPS 8
#define NTHREADS (NWARPS*32)
#define RS 16            // ring slots (raw rows); 16*4KB = 64KB dynamic smem

__device__ __forceinline__ int reflC(int c) {
    if (c < 0) c = -c;
    if (c > HH - 1) c = 2 * (HH - 1) - c;
    return c;
}

__device__ __forceinline__ void cpa16(uint32_t s, const float* g) {
    asm volatile("cp.async.cg.shared.global [%0], [%1], 16;" :: "r"(s), "l"(g) : "memory");
}
#define CPCOMMIT() asm volatile("cp.async.commit_group;" ::: "memory")
#define CPWAIT(n)  asm volatile("cp.async.wait_group %0;" :: "n"(n) : "memory")

__device__ __forceinline__ void stcs2(float* p, float a, float b) {
    asm volatile("st.global.cs.v2.f32 [%0], {%1,%2};" :: "l"(p), "f"(a), "f"(b) : "memory");
}

struct V4 { float s0, s1, d0, d1; };

// Shuffle-free row lift reading from an smem row (1024 contiguous floats).
__device__ __forceinline__ V4 rowlift(const float* rp,
                                      int loff, int offA, int offC,
                                      bool lEdge, bool rEdge) {
    const float4 B = *reinterpret_cast<const float4*>(rp + loff);   // raw[4j..4j+3]
    const float4 A = *reinterpret_cast<const float4*>(rp + offA);   // raw[4j-4..4j-1]
    const float4 C = *reinterpret_cast<const float4*>(rp + offC);   // raw[4j+4..4j+7]
    float dm1 = A.w - 0.5f * (A.x + B.x);   // d[2j-1]
    float d0  = B.y - 0.5f * (A.z + B.z);   // d[2j]
    float d1  = B.w - 0.5f * (B.x + C.x);   // d[2j+1]
    float d2  = C.y - 0.5f * (B.z + C.z);   // d[2j+2]
    if (lEdge) { dm1 = d1; d0 = B.y - B.z; }   // d[-1]=d[1]; even[-1]=even[1]
    if (rEdge) { d1 = B.w - B.x; d2 = d0; }    // even[512]=even[510]; d[512]=d[510]
    V4 r;
    r.s0 = B.x + 0.25f * (dm1 + d1);
    r.s1 = B.z + 0.25f * (d0 + d2);
    r.d0 = d0; r.d1 = d1;
    return r;
}

__global__ __launch_bounds__(NTHREADS, 3)
void ilwt2d_pipe_kernel(const float* __restrict__ x, float* __restrict__ out) {
    extern __shared__ __align__(16) float ring[];   // RS * NN floats

    const int tid  = threadIdx.x;
    const int lane = tid & 31;
    const int w    = tid >> 5;
    const int C0   = w * 64;
    const int i0   = blockIdx.x * TI;
    const int img  = blockIdx.y;
    const float* __restrict__ xp = x + (size_t)img * NN * NN;
    const int rbase = 2 * i0 - 4;

    const uint32_t sring = (uint32_t)__cvta_generic_to_shared(ring);

    // ---- stage logical offset k (slot k%RS); whole CTA covers one 4KB row ----
    #define STAGE(k) do {                                                       \
        int _row = rbase + (k);                                                 \
        _row = max(0, min(NN - 1, _row));                                       \
        cpa16(sring + (uint32_t)((((k) & (RS-1)) * NN + tid * 4) * 4),          \
              xp + (size_t)_row * NN + tid * 4);                                \
    } while (0)

    // prologue staging: 8 groups x 2 rows = offsets 0..15
    #pragma unroll
    for (int g = 0; g < 8; ++g) { STAGE(2*g); STAGE(2*g + 1); CPCOMMIT(); }
    CPWAIT(4);                      // offsets 0..7 complete (prologue needs <=6)
    __syncthreads();

    // consumer column setup
    const int loff = 2 * C0 + 4 * lane;
    const bool lEdge = (loff == 0);
    const bool rEdge = (loff == NN - 4);
    const int offA = lEdge ? loff : loff - 4;
    const int offC = rEdge ? loff : loff + 4;

    #define LIFTS(R) rowlift(ring + (((R) - rbase) & (RS-1)) * NN, \
                             loff, offA, offC, lEdge, rEdge)

    // ---- prologue: build column-lift pipeline state (reads offsets 0..6) ----
    V4 Ecur  = LIFTS(2 * i0);
    V4 Em    = LIFTS(2 * reflC(i0 - 1));
    V4 Em2   = LIFTS(2 * reflC(i0 - 2));
    V4 Om1   = LIFTS(2 * reflC(i0 - 1) + 1);
    V4 Dprev;
    Dprev.s0 = Om1.s0 - 0.5f * (Em2.s0 + Ecur.s0);
    Dprev.s1 = Om1.s1 - 0.5f * (Em2.s1 + Ecur.s1);
    Dprev.d0 = Om1.d0 - 0.5f * (Em2.d0 + Ecur.d0);
    Dprev.d1 = Om1.d1 - 0.5f * (Em2.d1 + Ecur.d1);
    V4 Enext = LIFTS(2 * reflC(i0 + 1));
    V4 O0    = LIFTS(2 * i0 + 1);
    V4 Dcur;
    Dcur.s0 = O0.s0 - 0.5f * (Em.s0 + Enext.s0);
    Dcur.s1 = O0.s1 - 0.5f * (Em.s1 + Enext.s1);
    Dcur.d0 = O0.d0 - 0.5f * (Em.d0 + Enext.d0);
    Dcur.d1 = O0.d1 - 0.5f * (Em.d1 + Enext.d1);
    __syncthreads();                // protect prologue reads from t=0 staging

    const int b = img / 3, ch = img - 3 * b;
    const size_t plane = (size_t)HH * HH;
    float* __restrict__ outb = out + (size_t)b * 12 * plane + (size_t)ch * plane;
    const int ocol = C0 + 2 * lane;

    // ---- main loop: stage 2 rows ahead, consume 2 rows, emit 1 output row ----
    for (int t = 0; t < TI; ++t) {
        const int i = i0 + t;

        STAGE(16 + 2*t); STAGE(17 + 2*t); CPCOMMIT();
        CPWAIT(4);                  // complete through offset 2t+9 (need 2t+8)
        __syncthreads();

        V4 En2 = LIFTS(2 * reflC(i + 2));          // offset 2t+8 (interior)
        V4 Oi1 = LIFTS(2 * reflC(i + 1) + 1);      // offset 2t+7 (interior)
        V4 Dnext;
        Dnext.s0 = Oi1.s0 - 0.5f * (Ecur.s0 + En2.s0);
        Dnext.s1 = Oi1.s1 - 0.5f * (Ecur.s1 + En2.s1);
        Dnext.d0 = Oi1.d0 - 0.5f * (Ecur.d0 + En2.d0);
        Dnext.d1 = Oi1.d1 - 0.5f * (Ecur.d1 + En2.d1);

        float2 ll = { Ecur.s0 + 0.25f * (Dprev.s0 + Dnext.s0),
                      Ecur.s1 + 0.25f * (Dprev.s1 + Dnext.s1) };
        float2 hl = { Ecur.d0 + 0.25f * (Dprev.d0 + Dnext.d0),
                      Ecur.d1 + 0.25f * (Dprev.d1 + Dnext.d1) };

        float* op = outb + (size_t)i * HH + ocol;
        stcs2(op,             ll.x, ll.y);
        stcs2(op + 3 * plane, Dcur.s0, Dcur.s1);
        stcs2(op + 6 * plane, hl.x, hl.y);
        stcs2(op + 9 * plane, Dcur.d0, Dcur.d1);

        Ecur = Enext; Enext = En2;
        Dprev = Dcur; Dcur = Dnext;
    }
    #undef STAGE
    #undef LIFTS
}

extern "C" void kernel_launch(void* const* d_in, const int* in_sizes, int n_in,
                              void* d_out, int out_size) {
    const float* x = (const float*)d_in[0];
    float* out = (float*)d_out;
    const int smem = RS * NN * sizeof(float);   // 65536
    cudaFuncSetAttribute(ilwt2d_pipe_kernel,
                         cudaFuncAttributeMaxDynamicSharedMemorySize, smem);
    dim3 grid(HH / TI, 24);   // 16 x 24 = 384 CTAs
    ilwt2d_pipe_kernel<<<grid, NTHREADS, smem>>>(x, out);
}